// round 1
// baseline (speedup 1.0000x reference)
#include <cuda_runtime.h>
#include <cstdint>

typedef unsigned long long ull;

// ---------------- problem constants ----------------
#define NPART 32
#define DIN   1024
#define HID   2048
#define DOUTP 256
#define L0 (HID*DIN)        // 2097152  W1 per-particle length / stride
#define L1 (HID)            // 2048     b1
#define L2 (DOUTP*HID)      // 524288   W2
#define L3 (DOUTP)          // 256      b2
#define SEG_B0 (L0)              // 2097152
#define SEG_B1 (SEG_B0 + L1)     // 2099200
#define SEG_B2 (SEG_B1 + L2)     // 2623488
#define P_TOT  (SEG_B2 + L3)     // 2623744   (divisible by 128)
#define NP     (P_TOT/2)         // 1311872 k-pairs
#define NCHUNK (P_TOT/128)       // 20498 chunks of 128 k
#define EPSV 0.1f

#define NBLK1 296
#define NWARP1 10
#define NBLK2 1184

// ---------------- scratch (static: no allocations allowed) ----------------
__device__ float  g_Gpart[NBLK1 * NWARP1 * 64];  // per-(block,warp-tile) partial Gram
__device__ float2 g_C2[1024];                    // duplicated coefficient matrix C[i][j] -> (c,c)

// upper-triangular 4x4 tile grid of 8x8 tiles over the 32x32 Gram
__constant__ int c_TBI[NWARP1] = {0,0,0,0,1,1,1,2,2,3};
__constant__ int c_TBJ[NWARP1] = {0,1,2,3,1,2,3,2,3,3};

// packed fp32x2 FMA (Blackwell): d.lo += a.lo*b.lo ; d.hi += a.hi*b.hi
__device__ __forceinline__ void ffma2(ull &d, ull a, ull b) {
    asm("fma.rn.f32x2 %0, %1, %2, %0;" : "+l"(d) : "l"(a), "l"(b));
}

// map global k (chunk-aligned use is warp-uniform) -> segment base/stride/local k
__device__ __forceinline__ const float* seg_base(int k,
        const float* __restrict__ W1, const float* __restrict__ b1,
        const float* __restrict__ W2, const float* __restrict__ b2,
        int &stride, int &kl) {
    if (k < SEG_B0) { stride = L0; kl = k;          return W1; }
    if (k < SEG_B1) { stride = L1; kl = k - SEG_B0; return b1; }
    if (k < SEG_B2) { stride = L2; kl = k - SEG_B1; return W2; }
    stride = L3; kl = k - SEG_B2; return b2;
}

// ---------------- pass 1: partial Gram (SYRK), warp = one 8x8 tile ----------------
__global__ __launch_bounds__(320, 1)
void gram_kernel(const float* __restrict__ W1, const float* __restrict__ b1,
                 const float* __restrict__ W2, const float* __restrict__ b2) {
    const int w    = threadIdx.x >> 5;
    const int lane = threadIdx.x & 31;
    const int bi = c_TBI[w], bj = c_TBJ[w];

    ull acc[64];
#pragma unroll
    for (int p = 0; p < 64; p++) acc[p] = 0ull;

    for (int c = blockIdx.x; c < NCHUNK; c += NBLK1) {
        const int k0 = c << 7;                // chunk of 128 k, never straddles a segment
        int stride, kl;
        const float* base = seg_base(k0, W1, b1, W2, b2, stride, kl);
        const float* p0 = base + kl + (lane << 2);   // lane owns 4 consecutive k (16B aligned)

        ulonglong2 av[8], bv[8];
        const float* pa = p0 + (bi * 8) * stride;
#pragma unroll
        for (int r = 0; r < 8; r++)
            av[r] = *reinterpret_cast<const ulonglong2*>(pa + r * stride);
        if (bi != bj) {
            const float* pb = p0 + (bj * 8) * stride;
#pragma unroll
            for (int r = 0; r < 8; r++)
                bv[r] = *reinterpret_cast<const ulonglong2*>(pb + r * stride);
        } else {
#pragma unroll
            for (int r = 0; r < 8; r++) bv[r] = av[r];
        }

#pragma unroll
        for (int r = 0; r < 8; r++)
#pragma unroll
            for (int q = 0; q < 8; q++) {
                ffma2(acc[r * 8 + q], av[r].x, bv[q].x);   // k, k+1
                ffma2(acc[r * 8 + q], av[r].y, bv[q].y);   // k+2, k+3
            }
    }

    // collapse f32x2 halves, butterfly-reduce across the 32 k-lanes, lane 0 writes partial
#pragma unroll
    for (int p = 0; p < 64; p++) {
        float v = __uint_as_float((unsigned)acc[p]) +
                  __uint_as_float((unsigned)(acc[p] >> 32));
        v += __shfl_xor_sync(0xffffffffu, v, 16);
        v += __shfl_xor_sync(0xffffffffu, v, 8);
        v += __shfl_xor_sync(0xffffffffu, v, 4);
        v += __shfl_xor_sync(0xffffffffu, v, 2);
        v += __shfl_xor_sync(0xffffffffu, v, 1);
        if (lane == 0) g_Gpart[(blockIdx.x * NWARP1 + w) * 64 + p] = v;
    }
}

// ---------------- pass 1b: reduce partials, build K, S, coefficient table ----------------
__global__ __launch_bounds__(1024, 1)
void coef_kernel() {
    __shared__ float Gs[32][32];
    __shared__ float Ks[32][33];
    __shared__ float Ssh[32];
    const int tid = threadIdx.x;

    if (tid < NWARP1 * 64) {
        float s0 = 0.f, s1 = 0.f, s2 = 0.f, s3 = 0.f;
        int b = 0;
        for (; b + 3 < NBLK1; b += 4) {
            s0 += g_Gpart[(b + 0) * (NWARP1 * 64) + tid];
            s1 += g_Gpart[(b + 1) * (NWARP1 * 64) + tid];
            s2 += g_Gpart[(b + 2) * (NWARP1 * 64) + tid];
            s3 += g_Gpart[(b + 3) * (NWARP1 * 64) + tid];
        }
        for (; b < NBLK1; b++) s0 += g_Gpart[b * (NWARP1 * 64) + tid];
        float s = (s0 + s1) + (s2 + s3);
        int w = tid / 64, pr = tid % 64, r = pr / 8, q = pr % 8;
        Gs[c_TBI[w] * 8 + r][c_TBJ[w] * 8 + q] = s;
    }
    __syncthreads();
    {   // mirror the lower tile-grid triangle
        int i = tid >> 5, j = tid & 31;
        if ((i >> 3) > (j >> 3)) Gs[i][j] = Gs[j][i];
    }
    __syncthreads();
    {   // RBF kernel
        int i = tid >> 5, j = tid & 31;
        float d2 = Gs[i][i] + Gs[j][j] - 2.f * Gs[i][j];
        d2 = fmaxf(d2, 0.f);
        Ks[i][j] = expf(-0.5f * d2);
    }
    __syncthreads();
    if (tid < 32) {       // S_i = sum_{j=1..31} K[i][j]
        float s = 0.f;
        for (int j = 1; j < 32; j++) s += Ks[tid][j];
        Ssh[tid] = s;
    }
    __syncthreads();
    {   // C[i][j]: out[i] = sum_j C[i][j] * theta[j]
        int i = tid >> 5, j = tid & 31;
        float v = (j >= 1) ? (EPSV / (float)NPART) * Ks[i][j] : 0.f;
        if (j == i) v += 1.f - 3.f * EPSV * Ssh[i] / (float)NPART;
        g_C2[tid] = make_float2(v, v);   // duplicated for f32x2
    }
}

// ---------------- pass 2: out = C @ theta, thread = one k-pair ----------------
__global__ __launch_bounds__(256)
void apply_kernel(const float* __restrict__ W1, const float* __restrict__ b1,
                  const float* __restrict__ W2, const float* __restrict__ b2,
                  float* __restrict__ out) {
    __shared__ ull C2s[1024];
    const ull* C2g = reinterpret_cast<const ull*>(g_C2);
    for (int idx = threadIdx.x; idx < 1024; idx += 256) C2s[idx] = C2g[idx];
    __syncthreads();

    ull* outp = reinterpret_cast<ull*>(out);
    const int gstep = gridDim.x * blockDim.x;

    for (int kp = blockIdx.x * 256 + threadIdx.x; kp < NP; kp += gstep) {
        const int k = kp << 1;
        int stride, kl;
        const float* base = seg_base(k, W1, b1, W2, b2, stride, kl);
        const float* p0 = base + kl;

        ull t[32];
#pragma unroll
        for (int j = 0; j < 32; j++)
            t[j] = *reinterpret_cast<const ull*>(p0 + j * stride);

#pragma unroll
        for (int ic = 0; ic < 4; ic++) {
            ull acc[8];
#pragma unroll
            for (int r = 0; r < 8; r++) acc[r] = 0ull;
#pragma unroll
            for (int j = 0; j < 32; j++) {
#pragma unroll
                for (int r = 0; r < 8; r++)
                    ffma2(acc[r], C2s[(ic * 8 + r) * 32 + j], t[j]);
            }
#pragma unroll
            for (int r = 0; r < 8; r++)
                outp[(ic * 8 + r) * NP + kp] = acc[r];
        }
    }
}

// ---------------- launch ----------------
extern "C" void kernel_launch(void* const* d_in, const int* in_sizes, int n_in,
                              void* d_out, int out_size) {
    const float* W1 = (const float*)d_in[0];
    const float* b1 = (const float*)d_in[1];
    const float* W2 = (const float*)d_in[2];
    const float* b2 = (const float*)d_in[3];
    float* out = (float*)d_out;

    gram_kernel<<<NBLK1, 320>>>(W1, b1, W2, b2);
    coef_kernel<<<1, 1024>>>();
    apply_kernel<<<NBLK2, 256>>>(W1, b1, W2, b2, out);
}